// round 8
// baseline (speedup 1.0000x reference)
#include <cuda_runtime.h>

// LogSparseAttention — B=2, L=S=2048, H=8, E=D=64, fp32.
// log_l=11 => row l attends to <=22 columns:
//   l < 22  : causal 0..l
//   l >= 22 : contiguous [l-10, l]  +  points { l-10-2^k : k=0..10, >=0 }
// One warp per (b,h,l) row. PAIR pattern: lower 16 lanes own the even column
// of each slot pair, upper 16 lanes the odd one; every LDG.128 fetches two
// complete 256B K/V rows (2 wavefronts per row — minimal).
// Scores stay RESIDENT per half (s[t] = score of column 2t+half in all 16
// lanes of the half) — no parking, no index/prob shuffles in AV. Inactive
// slots get s=-1e30 -> p==0 exactly, and their loads clamp to row 0.

#define BB 2
#define LL 2048
#define SS 2048
#define HH 8
#define EE 64
#define DD 64
#define WARPS_PER_BLOCK 8
#define FULL 0xffffffffu
#define ROW_STRIDE (HH * EE)   // 512 floats between consecutive seq positions
#define NT 11                  // slot pairs

// column index + active flag for slot c = 2t+half of row l (t compile-time
// after unroll, so the shift amount constant-folds).
__device__ __forceinline__ void slot_col(int l, bool big, int t, int half,
                                         int& jc, bool& act)
{
    int j;
    if (big) {
        if (2 * t + 1 <= 10) {              // t<=4: both columns contiguous
            j = l - 10 + 2 * t + half;
            act = true;
        } else if (2 * t >= 11) {           // t>=6: both columns log points
            const int sh = (1 << (2 * t - 11)) << half;
            j = l - 10 - sh;
            act = (j >= 0);
        } else {                            // t==5: c=10 contiguous / c=11 k=0
            j = half ? (l - 11) : l;        // l>=22 so l-11>=11>=0
            act = true;
        }
    } else {                                // causal row: col c, active c<=l
        j = 2 * t + half;
        act = (j <= l);
    }
    jc = act ? j : 0;                       // clamp: p==0 annihilates row 0
}

__global__ __launch_bounds__(WARPS_PER_BLOCK * 32)
void logsparse_attn_kernel(const float* __restrict__ q,
                           const float* __restrict__ k,
                           const float* __restrict__ v,
                           float* __restrict__ out)
{
    const int warpId = threadIdx.x >> 5;
    const int lane   = threadIdx.x & 31;
    const int half   = lane >> 4;          // 0: even column of pair, 1: odd
    const int hl     = lane & 15;          // owns 16B chunk hl of a 256B row
    const int r = blockIdx.x * WARPS_PER_BLOCK + warpId;   // 0 .. B*H*L-1
    const int b   = r / (HH * LL);
    const int rem = r - b * (HH * LL);
    const int h   = rem / LL;
    const int l   = rem - h * LL;
    const bool big = (l >= 22);

    // Q fragment: lane holds q[hl*4 .. hl*4+3] (duplicated across halves)
    const float* qrow = q + (((size_t)b * LL + l) * HH + h) * EE;
    const float4 q4 = reinterpret_cast<const float4*>(qrow)[hl];

    const float* kbase = k + ((size_t)b * SS * HH + h) * EE;
    const float* vbase = v + ((size_t)b * SS * HH + h) * EE;

    // ---- QK: 11 pair rounds; s[t] = score of column 2t+half, half-resident
    float s[NT];
    #pragma unroll
    for (int t = 0; t < NT; t++) {
        int jc; bool act;
        slot_col(l, big, t, half, jc, act);
        const float4 k4 = reinterpret_cast<const float4*>(
            kbase + (size_t)jc * ROW_STRIDE)[hl];
        float d = q4.x * k4.x;
        d = fmaf(q4.y, k4.y, d);
        d = fmaf(q4.z, k4.z, d);
        d = fmaf(q4.w, k4.w, d);
        d += __shfl_xor_sync(FULL, d, 8);   // intra-half reduce (both columns)
        d += __shfl_xor_sync(FULL, d, 4);
        d += __shfl_xor_sync(FULL, d, 2);
        d += __shfl_xor_sync(FULL, d, 1);
        s[t] = act ? d : -1e30f;
    }

    // ---- softmax over 22 slots: local reduce + ONE xor16 for max & denom
    float m = s[0];
    #pragma unroll
    for (int t = 1; t < NT; t++) m = fmaxf(m, s[t]);
    m = fmaxf(m, __shfl_xor_sync(FULL, m, 16));
    const float mm = -m * 0.125f;           // scale folded: exp((s-m)/sqrt(E))
    float p[NT];
    float denom = 0.0f;
    #pragma unroll
    for (int t = 0; t < NT; t++) {
        p[t] = __expf(fmaf(s[t], 0.125f, mm));   // inactive -> exactly 0
        denom += p[t];
    }
    denom += __shfl_xor_sync(FULL, denom, 16);
    const float invd = __fdividef(1.0f, denom);

    // ---- AV: p local, j recomputed (ALU); zero shuffles per round ----
    float4 acc = make_float4(0.0f, 0.0f, 0.0f, 0.0f);
    #pragma unroll
    for (int t = 0; t < NT; t++) {
        int jc; bool act;
        slot_col(l, big, t, half, jc, act);
        const float pc = p[t] * invd;
        const float4 v4 = reinterpret_cast<const float4*>(
            vbase + (size_t)jc * ROW_STRIDE)[hl];
        acc.x = fmaf(pc, v4.x, acc.x);
        acc.y = fmaf(pc, v4.y, acc.y);
        acc.z = fmaf(pc, v4.z, acc.z);
        acc.w = fmaf(pc, v4.w, acc.w);
    }
    // fold the two halves (even-column + odd-column partial sums)
    acc.x += __shfl_xor_sync(FULL, acc.x, 16);
    acc.y += __shfl_xor_sync(FULL, acc.y, 16);
    acc.z += __shfl_xor_sync(FULL, acc.z, 16);
    acc.w += __shfl_xor_sync(FULL, acc.w, 16);

    if (half == 0) {
        float4* orow = reinterpret_cast<float4*>(
            out + (((size_t)b * LL + l) * HH + h) * DD);
        orow[hl] = acc;
    }
}

extern "C" void kernel_launch(void* const* d_in, const int* in_sizes, int n_in,
                              void* d_out, int out_size)
{
    const float* q = (const float*)d_in[0];
    const float* k = (const float*)d_in[1];
    const float* v = (const float*)d_in[2];
    float* out = (float*)d_out;

    const int total_rows = BB * HH * LL;                   // 32768 warps
    const int blocks = total_rows / WARPS_PER_BLOCK;       // 4096
    logsparse_attn_kernel<<<blocks, WARPS_PER_BLOCK * 32>>>(q, k, v, out);
}

// round 13
// speedup vs baseline: 1.1515x; 1.1515x over previous
#include <cuda_runtime.h>

// LogSparseAttention — B=2, L=S=2048, H=8, E=D=64, fp32.
// log_l=11 => row l attends to <=22 columns:
//   l < 22  : causal 0..l
//   l >= 22 : contiguous [l-10, l]  +  points { l-10-2^k : k=0..10, >=0 }
// One warp per (b,h,l) row. PAIR pattern: lower 16 lanes own the even column
// of each slot pair, upper 16 the odd one; every LDG.128 fetches two complete
// 256B K/V rows. Intra-half dot reduce: 4-stage xor butterfly (redux.f32 does
// NOT exist on sm_103a). Scores stay half-resident; softmax is local + one
// xor16 for max and denom; AV accumulates unnormalized weights and scales
// once at the store. Warp-uniform BIG/causal template split keeps the hot
// path (l>=22, 99.5% of warps) free of per-slot predication for slots 0..5.

#define BB 2
#define LL 2048
#define SS 2048
#define HH 8
#define EE 64
#define DD 64
#define WARPS_PER_BLOCK 8
#define FULL 0xffffffffu
#define ROW_STRIDE (HH * EE)   // 512 floats between consecutive seq positions
#define NT 11                  // slot pairs

// column index for slot c = 2t+half of row l; t compile-time after unroll.
template <bool BIG>
__device__ __forceinline__ int slot_j(int l, int t, int half, bool& act) {
    if (BIG) {
        if (t <= 4) { act = true; return l - 10 + 2 * t + half; }   // contiguous
        if (t == 5) { act = true; return half ? (l - 11) : l; }     // c=10 / k=0
        const int sh = (1 << (2 * t - 11)) << half;                 // log points
        const int j = l - 10 - sh;
        act = (j >= 0);
        return act ? j : 0;                 // clamp: p==0 annihilates row 0
    } else {                                // causal row: col c, active c<=l
        const int j = 2 * t + half;
        act = (j <= l);
        return act ? j : 0;
    }
}

template <bool BIG>
__device__ __forceinline__ void compute_row(int l, int lane,
                                            const float* __restrict__ qrow,
                                            const float* __restrict__ kbase,
                                            const float* __restrict__ vbase,
                                            float* __restrict__ orow)
{
    const int half = lane >> 4;
    const int hl   = lane & 15;

    const float4 q4 = reinterpret_cast<const float4*>(qrow)[hl];

    // ---- QK: s[t] = score of column 2t+half, resident in all lanes of half
    float s[NT];
    #pragma unroll
    for (int t = 0; t < NT; t++) {
        bool act;
        const int jc = slot_j<BIG>(l, t, half, act);
        const float4 k4 = reinterpret_cast<const float4*>(
            kbase + (size_t)jc * ROW_STRIDE)[hl];
        float d = q4.x * k4.x;
        d = fmaf(q4.y, k4.y, d);
        d = fmaf(q4.z, k4.z, d);
        d = fmaf(q4.w, k4.w, d);
        d += __shfl_xor_sync(FULL, d, 8);   // intra-half butterfly (both halves)
        d += __shfl_xor_sync(FULL, d, 4);
        d += __shfl_xor_sync(FULL, d, 2);
        d += __shfl_xor_sync(FULL, d, 1);
        s[t] = act ? d : -1e30f;
    }

    // ---- softmax over 22 slots: local reduce + one xor16 each for max/denom
    float m = s[0];
    #pragma unroll
    for (int t = 1; t < NT; t++) m = fmaxf(m, s[t]);
    m = fmaxf(m, __shfl_xor_sync(FULL, m, 16));
    const float C  = 0.125f * 1.4426950408889634f;   // log2(e)/sqrt(E)
    const float d0 = -m * C;
    float denom = 0.0f;
    #pragma unroll
    for (int t = 0; t < NT; t++) {
        s[t] = exp2f(fmaf(s[t], C, d0));    // inactive -> exactly 0
        denom += s[t];
    }
    denom += __shfl_xor_sync(FULL, denom, 16);
    const float invd = __fdividef(1.0f, denom);

    // ---- AV with unnormalized weights; normalize once at the end ----
    float4 acc = make_float4(0.0f, 0.0f, 0.0f, 0.0f);
    #pragma unroll
    for (int t = 0; t < NT; t++) {
        bool act;
        const int jc = slot_j<BIG>(l, t, half, act);
        const float4 v4 = reinterpret_cast<const float4*>(
            vbase + (size_t)jc * ROW_STRIDE)[hl];
        acc.x = fmaf(s[t], v4.x, acc.x);
        acc.y = fmaf(s[t], v4.y, acc.y);
        acc.z = fmaf(s[t], v4.z, acc.z);
        acc.w = fmaf(s[t], v4.w, acc.w);
    }
    acc.x += __shfl_xor_sync(FULL, acc.x, 16);
    acc.y += __shfl_xor_sync(FULL, acc.y, 16);
    acc.z += __shfl_xor_sync(FULL, acc.z, 16);
    acc.w += __shfl_xor_sync(FULL, acc.w, 16);

    if (half == 0) {
        reinterpret_cast<float4*>(orow)[hl] =
            make_float4(acc.x * invd, acc.y * invd, acc.z * invd, acc.w * invd);
    }
}

__global__ __launch_bounds__(WARPS_PER_BLOCK * 32, 5)
void logsparse_attn_kernel(const float* __restrict__ q,
                           const float* __restrict__ k,
                           const float* __restrict__ v,
                           float* __restrict__ out)
{
    const int warpId = threadIdx.x >> 5;
    const int lane   = threadIdx.x & 31;
    const int r = blockIdx.x * WARPS_PER_BLOCK + warpId;   // 0 .. B*H*L-1
    const int b   = r / (HH * LL);
    const int rem = r - b * (HH * LL);
    const int h   = rem / LL;
    const int l   = rem - h * LL;

    const float* qrow  = q   + (((size_t)b * LL + l) * HH + h) * EE;
    const float* kbase = k   + ((size_t)b * SS * HH + h) * EE;
    const float* vbase = v   + ((size_t)b * SS * HH + h) * EE;
    float*       orow  = out + (((size_t)b * LL + l) * HH + h) * DD;

    if (l >= 22) compute_row<true >(l, lane, qrow, kbase, vbase, orow);
    else         compute_row<false>(l, lane, qrow, kbase, vbase, orow);
}

extern "C" void kernel_launch(void* const* d_in, const int* in_sizes, int n_in,
                              void* d_out, int out_size)
{
    const float* q = (const float*)d_in[0];
    const float* k = (const float*)d_in[1];
    const float* v = (const float*)d_in[2];
    float* out = (float*)d_out;

    const int total_rows = BB * HH * LL;                   // 32768 warps
    const int blocks = total_rows / WARPS_PER_BLOCK;       // 4096
    logsparse_attn_kernel<<<blocks, WARPS_PER_BLOCK * 32>>>(q, k, v, out);
}